// round 8
// baseline (speedup 1.0000x reference)
#include <cuda_runtime.h>
#include <math.h>

#define NMAX 100000
#define EMAX 600000
#define CIN 128
#define COUT 128

// ---------------- scratch (static __device__ globals; no runtime alloc) ----
__device__ float  g_normals[NMAX * 3];       // accumulation (scalar atomics)
__device__ float4 g_normals4[NMAX];          // normalized, 16B-aligned
__device__ float4 g_vtx4[NMAX];              // packed vertices, 16B-aligned
__device__ float  g_w[EMAX];
__device__ int    g_counts[NMAX];
__device__ int    g_start[NMAX];
__device__ int    g_cursor[NMAX];
__device__ float2 g_slots[EMAX];             // {w, bitcast(src)} per CSR slot
__device__ float  g_x[(size_t)NMAX * COUT];  // features @ Wlin + blin
__device__ float  g_colstats[2 * COUT];      // [0:128) sum, [128:256) sumsq
__device__ int    g_partials[128];

// ---------------- zero scratch + pack vertices into float4 ------------------
__global__ void zero_kernel(const float* __restrict__ vtx, int N) {
    int i = blockIdx.x * blockDim.x + threadIdx.x;
    int n3 = N * 3;
    if (i < n3) g_normals[i] = 0.f;
    if (i < N) {
        g_counts[i] = 0;
        g_vtx4[i] = make_float4(vtx[3 * i], vtx[3 * i + 1], vtx[3 * i + 2], 0.f);
    }
    if (i < 2 * COUT) g_colstats[i] = 0.f;
}

// ---------------- face normals: scatter cross products ----------------------
__global__ void face_kernel(const int* __restrict__ faces, int F) {
    int f = blockIdx.x * blockDim.x + threadIdx.x;
    if (f >= F) return;
    int i0 = faces[f], i1 = faces[F + f], i2 = faces[2 * F + f];
    float4 v0 = g_vtx4[i0];
    float4 v1 = g_vtx4[i1];
    float4 v2 = g_vtx4[i2];
    float ax = v1.x - v0.x, ay = v1.y - v0.y, az = v1.z - v0.z;
    float bx = v2.x - v0.x, by = v2.y - v0.y, bz = v2.z - v0.z;
    float nx = ay * bz - az * by;
    float ny = az * bx - ax * bz;
    float nz = ax * by - ay * bx;
    atomicAdd(&g_normals[3 * i0 + 0], nx);
    atomicAdd(&g_normals[3 * i0 + 1], ny);
    atomicAdd(&g_normals[3 * i0 + 2], nz);
    atomicAdd(&g_normals[3 * i1 + 0], nx);
    atomicAdd(&g_normals[3 * i1 + 1], ny);
    atomicAdd(&g_normals[3 * i1 + 2], nz);
    atomicAdd(&g_normals[3 * i2 + 0], nx);
    atomicAdd(&g_normals[3 * i2 + 1], ny);
    atomicAdd(&g_normals[3 * i2 + 2], nz);
}

__global__ void normalize_kernel(int N) {
    int i = blockIdx.x * blockDim.x + threadIdx.x;
    if (i >= N) return;
    float nx = g_normals[3 * i], ny = g_normals[3 * i + 1], nz = g_normals[3 * i + 2];
    float nn = sqrtf(nx * nx + ny * ny + nz * nz);
    float inv = 1.f / (nn + 1e-8f);
    g_normals4[i] = make_float4(nx * inv, ny * inv, nz * inv, 0.f);
}

// ---------------- per-edge metric MLP -> weight; count in-degree ------------
__global__ void edge_kernel(const int* __restrict__ edges,
                            const float* __restrict__ W1,
                            const float* __restrict__ b1,
                            const float* __restrict__ W2,
                            const float* __restrict__ b2, int E) {
    __shared__ float sW1[96], sb1[32], sW2[192], sb2[6];
    int tid = threadIdx.x;
    if (tid < 96) sW1[tid] = W1[tid];
    if (tid < 32) sb1[tid] = b1[tid];
    if (tid < 192) sW2[tid] = W2[tid];
    if (tid < 6) sb2[tid] = b2[tid];
    __syncthreads();

    int e = blockIdx.x * blockDim.x + tid;
    if (e >= E) return;
    int src = edges[e], dst = edges[E + e];

    float4 ps = g_vtx4[src];
    float4 pd = g_vtx4[dst];
    float4 nv = g_normals4[src];
    float dx = pd.x - ps.x, dy = pd.y - ps.y, dz = pd.z - ps.z;
    float dn = dx * nv.x + dy * nv.y + dz * nv.z;
    float t0 = dx - dn * nv.x, t1 = dy - dn * nv.y, t2 = dz - dn * nv.z;

    float th0 = sb2[0], th1 = sb2[1], th2 = sb2[2], th3 = sb2[3], th4 = sb2[4], th5 = sb2[5];
#pragma unroll
    for (int j = 0; j < 32; ++j) {
        float hv = t0 * sW1[j] + t1 * sW1[32 + j] + t2 * sW1[64 + j] + sb1[j];
        hv = fmaxf(hv, 0.f);
        th0 += hv * sW2[j * 6 + 0];
        th1 += hv * sW2[j * 6 + 1];
        th2 += hv * sW2[j * 6 + 2];
        th3 += hv * sW2[j * 6 + 3];
        th4 += hv * sW2[j * 6 + 4];
        th5 += hv * sW2[j * 6 + 5];
    }
    // S sym => q = t' S S t = ||S t||^2
    float u0 = th0 * t0 + th1 * t1 + th2 * t2;
    float u1 = th1 * t0 + th3 * t1 + th4 * t2;
    float u2 = th2 * t0 + th4 * t1 + th5 * t2;
    float q = u0 * u0 + u1 * u1 + u2 * u2;
    g_w[e] = expf(-q);
    atomicAdd(&g_counts[dst], 1);
}

// ---------------- 3-kernel exclusive scan over counts -----------------------
__device__ __forceinline__ int block_excl_scan(int v) {
    __shared__ int sm[32];
    int lane = threadIdx.x & 31, wid = threadIdx.x >> 5;
    int nw = blockDim.x >> 5;
    int incl = v;
#pragma unroll
    for (int o = 1; o < 32; o <<= 1) {
        int n = __shfl_up_sync(0xffffffffu, incl, o);
        if (lane >= o) incl += n;
    }
    if (lane == 31) sm[wid] = incl;
    __syncthreads();
    if (wid == 0) {
        int ws = (lane < nw) ? sm[lane] : 0;
#pragma unroll
        for (int o = 1; o < 32; o <<= 1) {
            int n = __shfl_up_sync(0xffffffffu, ws, o);
            if (lane >= o) ws += n;
        }
        if (lane < nw) sm[lane] = ws;
    }
    __syncthreads();
    int base = wid ? sm[wid - 1] : 0;
    return base + incl - v;
}

__global__ void scanA_kernel(int N) {
    __shared__ int sm[32];
    int i = blockIdx.x * 1024 + threadIdx.x;
    int v = (i < N) ? g_counts[i] : 0;
#pragma unroll
    for (int o = 16; o; o >>= 1) v += __shfl_down_sync(0xffffffffu, v, o);
    if ((threadIdx.x & 31) == 0) sm[threadIdx.x >> 5] = v;
    __syncthreads();
    if (threadIdx.x < 32) {
        int w = sm[threadIdx.x];
#pragma unroll
        for (int o = 16; o; o >>= 1) w += __shfl_down_sync(0xffffffffu, w, o);
        if (threadIdx.x == 0) g_partials[blockIdx.x] = w;
    }
}

__global__ void scanB_kernel(int NB) {
    int t = threadIdx.x;
    int v = (t < NB) ? g_partials[t] : 0;
    int ex = block_excl_scan(v);
    if (t < NB) g_partials[t] = ex;
}

__global__ void scanC_kernel(int N) {
    int i = blockIdx.x * 1024 + threadIdx.x;
    int v = (i < N) ? g_counts[i] : 0;
    int ex = block_excl_scan(v);
    if (i < N) {
        int s = g_partials[blockIdx.x] + ex;
        g_start[i] = s;
        g_cursor[i] = s;
    }
}

// ---------------- place edges into CSR slots --------------------------------
__global__ void place_kernel(const int* __restrict__ edges, int E) {
    int e = blockIdx.x * blockDim.x + threadIdx.x;
    if (e >= E) return;
    int src = edges[e], dst = edges[E + e];
    int slot = atomicAdd(&g_cursor[dst], 1);
    g_slots[slot] = make_float2(g_w[e], __int_as_float(src));
}

// ---------------- GEMM: x = features @ Wlin + blin  (fp32, packed f32x2) ----
__global__ void __launch_bounds__(256, 1)
gemm_kernel(const float* __restrict__ A, const float* __restrict__ W,
            const float* __restrict__ bias, int N) {
    __shared__ float Bs[64 * 128];  // 32 KB
    int tid = threadIdx.x;
    int tx = tid & 15, ty = tid >> 4;
    int row0 = blockIdx.x * 128 + ty * 8;

    unsigned long long acc[8][4];
#pragma unroll
    for (int i = 0; i < 8; ++i)
#pragma unroll
        for (int j = 0; j < 4; ++j) acc[i][j] = 0ull;

    const float4* A4 = (const float4*)A;
    const float4* W4 = (const float4*)W;
    float4* Bs4 = (float4*)Bs;

    for (int h = 0; h < 2; ++h) {
        __syncthreads();
#pragma unroll
        for (int i = 0; i < 8; ++i) Bs4[tid + i * 256] = W4[h * 2048 + tid + i * 256];
        __syncthreads();

        for (int k4 = 0; k4 < 16; ++k4) {
            int kk = h * 16 + k4;
            float4 av[8];
#pragma unroll
            for (int i = 0; i < 8; ++i) {
                int r = row0 + i;
                av[i] = (r < N) ? __ldg(&A4[(size_t)r * 32 + kk])
                                : make_float4(0.f, 0.f, 0.f, 0.f);
            }
#pragma unroll
            for (int s = 0; s < 4; ++s) {
                const unsigned long long* brow =
                    (const unsigned long long*)&Bs[(k4 * 4 + s) * 128];
                unsigned long long b0 = brow[tx];
                unsigned long long b1 = brow[16 + tx];
                unsigned long long b2 = brow[32 + tx];
                unsigned long long b3 = brow[48 + tx];
#pragma unroll
                for (int i = 0; i < 8; ++i) {
                    float a = (s == 0) ? av[i].x : (s == 1) ? av[i].y
                              : (s == 2) ? av[i].z : av[i].w;
                    unsigned int au = __float_as_uint(a);
                    unsigned long long pa;
                    asm("mov.b64 %0, {%1, %2};" : "=l"(pa) : "r"(au), "r"(au));
                    asm("fma.rn.f32x2 %0, %1, %2, %0;" : "+l"(acc[i][0]) : "l"(pa), "l"(b0));
                    asm("fma.rn.f32x2 %0, %1, %2, %0;" : "+l"(acc[i][1]) : "l"(pa), "l"(b1));
                    asm("fma.rn.f32x2 %0, %1, %2, %0;" : "+l"(acc[i][2]) : "l"(pa), "l"(b2));
                    asm("fma.rn.f32x2 %0, %1, %2, %0;" : "+l"(acc[i][3]) : "l"(pa), "l"(b3));
                }
            }
        }
    }

    const unsigned long long* bias2 = (const unsigned long long*)bias;
    unsigned long long bb[4];
#pragma unroll
    for (int j = 0; j < 4; ++j) bb[j] = bias2[j * 16 + tx];

#pragma unroll
    for (int i = 0; i < 8; ++i) {
        int r = row0 + i;
        if (r >= N) break;
        unsigned long long* orow = (unsigned long long*)&g_x[(size_t)r * 128];
#pragma unroll
        for (int j = 0; j < 4; ++j) {
            unsigned long long res;
            asm("add.rn.f32x2 %0, %1, %2;" : "=l"(res) : "l"(acc[i][j]), "l"(bb[j]));
            orow[j * 16 + tx] = res;
        }
    }
}

// ---- warp-per-vertex weighted-mean aggregation + fused column stats --------
__global__ void __launch_bounds__(256, 2)
aggregate_kernel(float* __restrict__ out, int N) {
    __shared__ float sstat[256];
    int tid = threadIdx.x;
    sstat[tid] = 0.f;
    __syncthreads();

    int lane = tid & 31;
    int wwarp = tid >> 5;
    int vstart = blockIdx.x * 8 + wwarp;
    int vstride = gridDim.x * 8;

    const float4* X4 = (const float4*)g_x;
    float s0 = 0.f, s1 = 0.f, s2 = 0.f, s3 = 0.f;
    float q0 = 0.f, q1 = 0.f, q2 = 0.f, q3 = 0.f;

    for (int v = vstart; v < N; v += vstride) {
        int base = g_start[v];
        int deg = g_counts[v];
        float4 acc = make_float4(0.f, 0.f, 0.f, 0.f);
        float wsum = 0.f;
        for (int it = 0; it < deg; ++it) {
            float2 sl = g_slots[base + it];
            float we = sl.x;
            int src = __float_as_int(sl.y);
            float4 xv = X4[(size_t)src * 32 + lane];
            acc.x += we * xv.x; acc.y += we * xv.y;
            acc.z += we * xv.z; acc.w += we * xv.w;
            wsum += we;
        }
        float inv = 1.f / (wsum + 1e-5f);
        float4 o = make_float4(acc.x * inv, acc.y * inv, acc.z * inv, acc.w * inv);
        ((float4*)out)[(size_t)v * 32 + lane] = o;
        s0 += o.x; s1 += o.y; s2 += o.z; s3 += o.w;
        q0 += o.x * o.x; q1 += o.y * o.y; q2 += o.z * o.z; q3 += o.w * o.w;
    }

    int c = lane * 4;
    atomicAdd(&sstat[c + 0], s0);
    atomicAdd(&sstat[c + 1], s1);
    atomicAdd(&sstat[c + 2], s2);
    atomicAdd(&sstat[c + 3], s3);
    atomicAdd(&sstat[128 + c + 0], q0);
    atomicAdd(&sstat[128 + c + 1], q1);
    atomicAdd(&sstat[128 + c + 2], q2);
    atomicAdd(&sstat[128 + c + 3], q3);
    __syncthreads();
    atomicAdd(&g_colstats[tid], sstat[tid]);
}

// ---------------- normalize + ELU (stats folded in) -------------------------
__global__ void norm_elu_kernel(float* __restrict__ out, int N) {
    __shared__ float smu[128], sinv[128];
    int tid = threadIdx.x;
    if (tid < 128) {
        float s = g_colstats[tid], q = g_colstats[128 + tid];
        float mu = s / (float)N;
        float var = (q - (float)N * mu * mu) / (float)(N - 1);
        var = fmaxf(var, 0.f);
        smu[tid] = mu;
        sinv[tid] = 1.f / (sqrtf(var) + 1e-5f);
    }
    __syncthreads();

    int total = N * 32;  // float4 count
    for (int i = blockIdx.x * blockDim.x + tid; i < total;
         i += gridDim.x * blockDim.x) {
        float4 v = ((float4*)out)[i];
        int c = (i & 31) * 4;
        float z;
        z = (v.x - smu[c + 0]) * sinv[c + 0]; v.x = z > 0.f ? z : expm1f(z);
        z = (v.y - smu[c + 1]) * sinv[c + 1]; v.y = z > 0.f ? z : expm1f(z);
        z = (v.z - smu[c + 2]) * sinv[c + 2]; v.z = z > 0.f ? z : expm1f(z);
        z = (v.w - smu[c + 3]) * sinv[c + 3]; v.w = z > 0.f ? z : expm1f(z);
        ((float4*)out)[i] = v;
    }
}

// ---------------- launcher ---------------------------------------------------
extern "C" void kernel_launch(void* const* d_in, const int* in_sizes, int n_in,
                              void* d_out, int out_size) {
    const float* features = (const float*)d_in[0];
    const float* vertices = (const float*)d_in[1];
    const int*   edges    = (const int*)d_in[2];
    const int*   faces    = (const int*)d_in[3];
    const float* W1       = (const float*)d_in[4];
    const float* b1       = (const float*)d_in[5];
    const float* W2       = (const float*)d_in[6];
    const float* b2       = (const float*)d_in[7];
    const float* Wlin     = (const float*)d_in[8];
    const float* blin     = (const float*)d_in[9];
    float* out = (float*)d_out;

    int N = in_sizes[0] / CIN;
    int E = in_sizes[2] / 2;
    int F = in_sizes[3] / 3;
    if (N > NMAX) N = NMAX;
    if (E > EMAX) E = EMAX;

    static cudaStream_t s2 = nullptr;
    static cudaEvent_t evFork = nullptr, evJoin = nullptr;
    if (s2 == nullptr) {
        cudaStreamCreateWithFlags(&s2, cudaStreamNonBlocking);
        cudaEventCreateWithFlags(&evFork, cudaEventDisableTiming);
        cudaEventCreateWithFlags(&evJoin, cudaEventDisableTiming);
    }

    // Fork: GEMM is independent of the geometry chain; run it on s2.
    cudaEventRecord(evFork, 0);
    cudaStreamWaitEvent(s2, evFork, 0);
    gemm_kernel<<<(N + 127) / 128, 256, 0, s2>>>(features, Wlin, blin, N);
    cudaEventRecord(evJoin, s2);

    // Geometry chain on the default stream.
    int zgrid = (N * 3 + 255) / 256;
    zero_kernel<<<zgrid, 256>>>(vertices, N);

    face_kernel<<<(F + 255) / 256, 256>>>(faces, F);
    normalize_kernel<<<(N + 255) / 256, 256>>>(N);

    edge_kernel<<<(E + 255) / 256, 256>>>(edges, W1, b1, W2, b2, E);

    int NB = (N + 1023) / 1024;
    scanA_kernel<<<NB, 1024>>>(N);
    scanB_kernel<<<1, 128>>>(NB);
    scanC_kernel<<<NB, 1024>>>(N);

    place_kernel<<<(E + 255) / 256, 256>>>(edges, E);

    // Join: aggregation needs both the CSR (default stream) and x (s2).
    cudaStreamWaitEvent(0, evJoin, 0);

    aggregate_kernel<<<1184, 256>>>(out, N);
    norm_elu_kernel<<<1184, 256>>>(out, N);
}

// round 9
// speedup vs baseline: 1.5126x; 1.5126x over previous
#include <cuda_runtime.h>
#include <math.h>

// Problem constants (fixed shapes; runtime sizes derived from in_sizes and
// clamped against these capacities).
#define NMAX 100000
#define EMAX 600000
#define CIN 128
#define COUT 128

// ---------------- scratch (static __device__ globals; no runtime alloc) ----
__device__ float  g_normals[NMAX * 3];
__device__ float  g_w[EMAX];
__device__ int    g_counts[NMAX];    // in-degree (preserved for aggregation)
__device__ int    g_start[NMAX];     // CSR exclusive offsets (preserved)
__device__ int    g_cursor[NMAX];    // consumed by placement
__device__ float2 g_slots[EMAX];     // {w, bitcast(src)} per CSR slot
__device__ float  g_x[(size_t)NMAX * COUT];  // features @ Wlin + blin
__device__ float  g_colstats[2 * COUT];      // [0:128) sum, [128:256) sumsq
__device__ int    g_partials[128];   // scan block partials (<= 98 used)

// ---------------- zero scratch that is accumulated into ---------------------
__global__ void zero_kernel(int N) {
    int i = blockIdx.x * blockDim.x + threadIdx.x;
    int n3 = N * 3;
    if (i < n3) g_normals[i] = 0.f;
    if (i < N) g_counts[i] = 0;
    if (i < 2 * COUT) g_colstats[i] = 0.f;
}

// ---------------- face normals: scatter cross products ----------------------
__global__ void face_kernel(const float* __restrict__ vtx,
                            const int* __restrict__ faces, int F) {
    int f = blockIdx.x * blockDim.x + threadIdx.x;
    if (f >= F) return;
    int i0 = faces[f], i1 = faces[F + f], i2 = faces[2 * F + f];
    float v0x = vtx[3 * i0], v0y = vtx[3 * i0 + 1], v0z = vtx[3 * i0 + 2];
    float v1x = vtx[3 * i1], v1y = vtx[3 * i1 + 1], v1z = vtx[3 * i1 + 2];
    float v2x = vtx[3 * i2], v2y = vtx[3 * i2 + 1], v2z = vtx[3 * i2 + 2];
    float ax = v1x - v0x, ay = v1y - v0y, az = v1z - v0z;
    float bx = v2x - v0x, by = v2y - v0y, bz = v2z - v0z;
    float nx = ay * bz - az * by;
    float ny = az * bx - ax * bz;
    float nz = ax * by - ay * bx;
    atomicAdd(&g_normals[3 * i0 + 0], nx);
    atomicAdd(&g_normals[3 * i0 + 1], ny);
    atomicAdd(&g_normals[3 * i0 + 2], nz);
    atomicAdd(&g_normals[3 * i1 + 0], nx);
    atomicAdd(&g_normals[3 * i1 + 1], ny);
    atomicAdd(&g_normals[3 * i1 + 2], nz);
    atomicAdd(&g_normals[3 * i2 + 0], nx);
    atomicAdd(&g_normals[3 * i2 + 1], ny);
    atomicAdd(&g_normals[3 * i2 + 2], nz);
}

__global__ void normalize_kernel(int N) {
    int i = blockIdx.x * blockDim.x + threadIdx.x;
    if (i >= N) return;
    float nx = g_normals[3 * i], ny = g_normals[3 * i + 1], nz = g_normals[3 * i + 2];
    float nn = sqrtf(nx * nx + ny * ny + nz * nz);
    float inv = 1.f / (nn + 1e-8f);
    g_normals[3 * i] = nx * inv;
    g_normals[3 * i + 1] = ny * inv;
    g_normals[3 * i + 2] = nz * inv;
}

// ---------------- per-edge metric MLP -> weight; count in-degree ------------
__global__ void edge_kernel(const float* __restrict__ vtx,
                            const int* __restrict__ edges,
                            const float* __restrict__ W1,
                            const float* __restrict__ b1,
                            const float* __restrict__ W2,
                            const float* __restrict__ b2, int E) {
    __shared__ float sW1[96], sb1[32], sW2[192], sb2[6];
    int tid = threadIdx.x;
    if (tid < 96) sW1[tid] = W1[tid];
    if (tid < 32) sb1[tid] = b1[tid];
    if (tid < 192) sW2[tid] = W2[tid];
    if (tid < 6) sb2[tid] = b2[tid];
    __syncthreads();

    int e = blockIdx.x * blockDim.x + tid;
    if (e >= E) return;
    int src = edges[e], dst = edges[E + e];

    float sx = vtx[3 * src], sy = vtx[3 * src + 1], sz = vtx[3 * src + 2];
    float dx = vtx[3 * dst] - sx;
    float dy = vtx[3 * dst + 1] - sy;
    float dz = vtx[3 * dst + 2] - sz;
    float nx = g_normals[3 * src], ny = g_normals[3 * src + 1], nz = g_normals[3 * src + 2];
    float dn = dx * nx + dy * ny + dz * nz;
    float t0 = dx - dn * nx, t1 = dy - dn * ny, t2 = dz - dn * nz;

    float th0 = sb2[0], th1 = sb2[1], th2 = sb2[2], th3 = sb2[3], th4 = sb2[4], th5 = sb2[5];
#pragma unroll
    for (int j = 0; j < 32; ++j) {
        float hv = t0 * sW1[j] + t1 * sW1[32 + j] + t2 * sW1[64 + j] + sb1[j];
        hv = fmaxf(hv, 0.f);
        th0 += hv * sW2[j * 6 + 0];
        th1 += hv * sW2[j * 6 + 1];
        th2 += hv * sW2[j * 6 + 2];
        th3 += hv * sW2[j * 6 + 3];
        th4 += hv * sW2[j * 6 + 4];
        th5 += hv * sW2[j * 6 + 5];
    }
    // S = [[t0,t1,t2],[t1,t3,t4],[t2,t4,t5]]; q = t'SSt = ||S t||^2 (S sym)
    float u0 = th0 * t0 + th1 * t1 + th2 * t2;
    float u1 = th1 * t0 + th3 * t1 + th4 * t2;
    float u2 = th2 * t0 + th4 * t1 + th5 * t2;
    float q = u0 * u0 + u1 * u1 + u2 * u2;
    g_w[e] = expf(-q);
    atomicAdd(&g_counts[dst], 1);
}

// ---------------- 3-kernel exclusive scan over counts -----------------------
__device__ __forceinline__ int block_excl_scan(int v) {
    __shared__ int sm[32];
    int lane = threadIdx.x & 31, wid = threadIdx.x >> 5;
    int nw = blockDim.x >> 5;
    int incl = v;
#pragma unroll
    for (int o = 1; o < 32; o <<= 1) {
        int n = __shfl_up_sync(0xffffffffu, incl, o);
        if (lane >= o) incl += n;
    }
    if (lane == 31) sm[wid] = incl;
    __syncthreads();
    if (wid == 0) {
        int ws = (lane < nw) ? sm[lane] : 0;
#pragma unroll
        for (int o = 1; o < 32; o <<= 1) {
            int n = __shfl_up_sync(0xffffffffu, ws, o);
            if (lane >= o) ws += n;
        }
        if (lane < nw) sm[lane] = ws;
    }
    __syncthreads();
    int base = wid ? sm[wid - 1] : 0;
    return base + incl - v;
}

__global__ void scanA_kernel(int N) {  // block sums of counts
    __shared__ int sm[32];
    int i = blockIdx.x * 1024 + threadIdx.x;
    int v = (i < N) ? g_counts[i] : 0;
#pragma unroll
    for (int o = 16; o; o >>= 1) v += __shfl_down_sync(0xffffffffu, v, o);
    if ((threadIdx.x & 31) == 0) sm[threadIdx.x >> 5] = v;
    __syncthreads();
    if (threadIdx.x < 32) {
        int w = sm[threadIdx.x];
#pragma unroll
        for (int o = 16; o; o >>= 1) w += __shfl_down_sync(0xffffffffu, w, o);
        if (threadIdx.x == 0) g_partials[blockIdx.x] = w;
    }
}

__global__ void scanB_kernel(int NB) {  // 1 block: scan partials in-place
    int t = threadIdx.x;
    int v = (t < NB) ? g_partials[t] : 0;
    int ex = block_excl_scan(v);
    if (t < NB) g_partials[t] = ex;
}

__global__ void scanC_kernel(int N) {  // final offsets
    int i = blockIdx.x * 1024 + threadIdx.x;
    int v = (i < N) ? g_counts[i] : 0;
    int ex = block_excl_scan(v);
    if (i < N) {
        int s = g_partials[blockIdx.x] + ex;
        g_start[i] = s;
        g_cursor[i] = s;
    }
}

// ---------------- place edges into CSR slots --------------------------------
__global__ void place_kernel(const int* __restrict__ edges, int E) {
    int e = blockIdx.x * blockDim.x + threadIdx.x;
    if (e >= E) return;
    int src = edges[e], dst = edges[E + e];
    int slot = atomicAdd(&g_cursor[dst], 1);
    g_slots[slot] = make_float2(g_w[e], __int_as_float(src));
}

// ---------------- GEMM: x = features @ Wlin + blin  (fp32, packed f32x2) ----
__global__ void __launch_bounds__(256, 1)
gemm_kernel(const float* __restrict__ A, const float* __restrict__ W,
            const float* __restrict__ bias, int N) {
    __shared__ float Bs[64 * 128];  // 32 KB
    int tid = threadIdx.x;
    int tx = tid & 15, ty = tid >> 4;
    int row0 = blockIdx.x * 128 + ty * 8;

    unsigned long long acc[8][4];
#pragma unroll
    for (int i = 0; i < 8; ++i)
#pragma unroll
        for (int j = 0; j < 4; ++j) acc[i][j] = 0ull;

    const float4* A4 = (const float4*)A;
    const float4* W4 = (const float4*)W;
    float4* Bs4 = (float4*)Bs;

    for (int h = 0; h < 2; ++h) {
        __syncthreads();
#pragma unroll
        for (int i = 0; i < 8; ++i) Bs4[tid + i * 256] = W4[h * 2048 + tid + i * 256];
        __syncthreads();

        for (int k4 = 0; k4 < 16; ++k4) {
            int kk = h * 16 + k4;
            float4 av[8];
#pragma unroll
            for (int i = 0; i < 8; ++i) {
                int r = row0 + i;
                av[i] = (r < N) ? __ldg(&A4[(size_t)r * 32 + kk])
                                : make_float4(0.f, 0.f, 0.f, 0.f);
            }
#pragma unroll
            for (int s = 0; s < 4; ++s) {
                const unsigned long long* brow =
                    (const unsigned long long*)&Bs[(k4 * 4 + s) * 128];
                unsigned long long b0 = brow[tx];
                unsigned long long b1 = brow[16 + tx];
                unsigned long long b2 = brow[32 + tx];
                unsigned long long b3 = brow[48 + tx];
#pragma unroll
                for (int i = 0; i < 8; ++i) {
                    float a = (s == 0) ? av[i].x : (s == 1) ? av[i].y
                              : (s == 2) ? av[i].z : av[i].w;
                    unsigned int au = __float_as_uint(a);
                    unsigned long long pa;
                    asm("mov.b64 %0, {%1, %2};" : "=l"(pa) : "r"(au), "r"(au));
                    asm("fma.rn.f32x2 %0, %1, %2, %0;" : "+l"(acc[i][0]) : "l"(pa), "l"(b0));
                    asm("fma.rn.f32x2 %0, %1, %2, %0;" : "+l"(acc[i][1]) : "l"(pa), "l"(b1));
                    asm("fma.rn.f32x2 %0, %1, %2, %0;" : "+l"(acc[i][2]) : "l"(pa), "l"(b2));
                    asm("fma.rn.f32x2 %0, %1, %2, %0;" : "+l"(acc[i][3]) : "l"(pa), "l"(b3));
                }
            }
        }
    }

    const unsigned long long* bias2 = (const unsigned long long*)bias;
    unsigned long long bb[4];
#pragma unroll
    for (int j = 0; j < 4; ++j) bb[j] = bias2[j * 16 + tx];

#pragma unroll
    for (int i = 0; i < 8; ++i) {
        int r = row0 + i;
        if (r >= N) break;
        unsigned long long* orow = (unsigned long long*)&g_x[(size_t)r * 128];
#pragma unroll
        for (int j = 0; j < 4; ++j) {
            unsigned long long res;
            asm("add.rn.f32x2 %0, %1, %2;" : "=l"(res) : "l"(acc[i][j]), "l"(bb[j]));
            orow[j * 16 + tx] = res;
        }
    }
}

// ---- warp-per-vertex weighted-mean aggregation + fused column stats --------
// Persistent grid-stride over vertices. Degree loop unrolled x2 so two slot
// reads and two 512B x-row gathers are in flight together (MLP=2 vs 1).
// No occupancy cap: let the regs decide (higher residency hides L2 latency).
__global__ void __launch_bounds__(256)
aggregate_kernel(float* __restrict__ out, int N) {
    __shared__ float sstat[256];
    int tid = threadIdx.x;
    sstat[tid] = 0.f;
    __syncthreads();

    int lane = tid & 31;
    int wwarp = tid >> 5;
    int vstart = blockIdx.x * 8 + wwarp;
    int vstride = gridDim.x * 8;

    const float4* X4 = (const float4*)g_x;
    float s0 = 0.f, s1 = 0.f, s2 = 0.f, s3 = 0.f;
    float q0 = 0.f, q1 = 0.f, q2 = 0.f, q3 = 0.f;

    for (int v = vstart; v < N; v += vstride) {
        int base = g_start[v];
        int deg = g_counts[v];
        float4 acc = make_float4(0.f, 0.f, 0.f, 0.f);
        float wsum = 0.f;
        int it = 0;
        for (; it + 1 < deg; it += 2) {
            float2 sa = g_slots[base + it];
            float2 sb = g_slots[base + it + 1];
            int srca = __float_as_int(sa.y);
            int srcb = __float_as_int(sb.y);
            float4 xa = X4[(size_t)srca * 32 + lane];
            float4 xb = X4[(size_t)srcb * 32 + lane];
            acc.x += sa.x * xa.x; acc.y += sa.x * xa.y;
            acc.z += sa.x * xa.z; acc.w += sa.x * xa.w;
            acc.x += sb.x * xb.x; acc.y += sb.x * xb.y;
            acc.z += sb.x * xb.z; acc.w += sb.x * xb.w;
            wsum += sa.x + sb.x;
        }
        if (it < deg) {
            float2 sl = g_slots[base + it];
            int src = __float_as_int(sl.y);
            float4 xv = X4[(size_t)src * 32 + lane];
            acc.x += sl.x * xv.x; acc.y += sl.x * xv.y;
            acc.z += sl.x * xv.z; acc.w += sl.x * xv.w;
            wsum += sl.x;
        }
        float inv = 1.f / (wsum + 1e-5f);
        float4 o = make_float4(acc.x * inv, acc.y * inv, acc.z * inv, acc.w * inv);
        ((float4*)out)[(size_t)v * 32 + lane] = o;
        s0 += o.x; s1 += o.y; s2 += o.z; s3 += o.w;
        q0 += o.x * o.x; q1 += o.y * o.y; q2 += o.z * o.z; q3 += o.w * o.w;
    }

    int c = lane * 4;
    atomicAdd(&sstat[c + 0], s0);
    atomicAdd(&sstat[c + 1], s1);
    atomicAdd(&sstat[c + 2], s2);
    atomicAdd(&sstat[c + 3], s3);
    atomicAdd(&sstat[128 + c + 0], q0);
    atomicAdd(&sstat[128 + c + 1], q1);
    atomicAdd(&sstat[128 + c + 2], q2);
    atomicAdd(&sstat[128 + c + 3], q3);
    __syncthreads();
    atomicAdd(&g_colstats[tid], sstat[tid]);
}

// ---------------- normalize + ELU (stats finalization folded in) ------------
__global__ void norm_elu_kernel(float* __restrict__ out, int N) {
    __shared__ float smu[128], sinv[128];
    int tid = threadIdx.x;
    if (tid < 128) {
        float s = g_colstats[tid], q = g_colstats[128 + tid];
        float mu = s / (float)N;
        float var = (q - (float)N * mu * mu) / (float)(N - 1);
        var = fmaxf(var, 0.f);
        smu[tid] = mu;
        sinv[tid] = 1.f / (sqrtf(var) + 1e-5f);
    }
    __syncthreads();

    int total = N * 32;  // float4 count
    for (int i = blockIdx.x * blockDim.x + tid; i < total;
         i += gridDim.x * blockDim.x) {
        float4 v = ((float4*)out)[i];
        int c = (i & 31) * 4;
        float z;
        z = (v.x - smu[c + 0]) * sinv[c + 0]; v.x = z > 0.f ? z : expm1f(z);
        z = (v.y - smu[c + 1]) * sinv[c + 1]; v.y = z > 0.f ? z : expm1f(z);
        z = (v.z - smu[c + 2]) * sinv[c + 2]; v.z = z > 0.f ? z : expm1f(z);
        z = (v.w - smu[c + 3]) * sinv[c + 3]; v.w = z > 0.f ? z : expm1f(z);
        ((float4*)out)[i] = v;
    }
}

// ---------------- launcher ---------------------------------------------------
extern "C" void kernel_launch(void* const* d_in, const int* in_sizes, int n_in,
                              void* d_out, int out_size) {
    const float* features = (const float*)d_in[0];
    const float* vertices = (const float*)d_in[1];
    const int*   edges    = (const int*)d_in[2];
    const int*   faces    = (const int*)d_in[3];
    const float* W1       = (const float*)d_in[4];
    const float* b1       = (const float*)d_in[5];
    const float* W2       = (const float*)d_in[6];
    const float* b2       = (const float*)d_in[7];
    const float* Wlin     = (const float*)d_in[8];
    const float* blin     = (const float*)d_in[9];
    float* out = (float*)d_out;

    int N = in_sizes[0] / CIN;
    int E = in_sizes[2] / 2;
    int F = in_sizes[3] / 3;
    if (N > NMAX) N = NMAX;
    if (E > EMAX) E = EMAX;

    // One-time host resources (created on the uncaptured correctness call;
    // no device memory involved).
    static cudaStream_t s2 = nullptr;
    static cudaEvent_t evFork = nullptr, evJoin = nullptr;
    if (s2 == nullptr) {
        cudaStreamCreateWithFlags(&s2, cudaStreamNonBlocking);
        cudaEventCreateWithFlags(&evFork, cudaEventDisableTiming);
        cudaEventCreateWithFlags(&evJoin, cudaEventDisableTiming);
    }

    // Fork: GEMM is independent of the geometry chain; run it on s2.
    cudaEventRecord(evFork, 0);
    cudaStreamWaitEvent(s2, evFork, 0);
    gemm_kernel<<<(N + 127) / 128, 256, 0, s2>>>(features, Wlin, blin, N);
    cudaEventRecord(evJoin, s2);

    // Geometry chain on the default stream.
    int zgrid = (N * 3 + 255) / 256;
    zero_kernel<<<zgrid, 256>>>(N);

    face_kernel<<<(F + 255) / 256, 256>>>(vertices, faces, F);
    normalize_kernel<<<(N + 255) / 256, 256>>>(N);

    edge_kernel<<<(E + 255) / 256, 256>>>(vertices, edges, W1, b1, W2, b2, E);

    int NB = (N + 1023) / 1024;
    scanA_kernel<<<NB, 1024>>>(N);
    scanB_kernel<<<1, 128>>>(NB);
    scanC_kernel<<<NB, 1024>>>(N);

    place_kernel<<<(E + 255) / 256, 256>>>(edges, E);

    // Join: aggregation needs both the CSR (default stream) and x (s2).
    cudaStreamWaitEvent(0, evJoin, 0);

    aggregate_kernel<<<1184, 256>>>(out, N);
    norm_elu_kernel<<<1184, 256>>>(out, N);
}

// round 11
// speedup vs baseline: 1.5522x; 1.0262x over previous
#include <cuda_runtime.h>
#include <math.h>

#define NMAX 100000
#define EMAX 600000
#define CIN 128
#define COUT 128

// ---------------- scratch (static __device__ globals; no runtime alloc) ----
__device__ float  g_normals[NMAX * 3];       // accumulated face normals (raw)
__device__ int    g_counts[NMAX];            // in-degree
__device__ int    g_start[NMAX];             // CSR exclusive offsets
__device__ int    g_cursor[NMAX];            // consumed by placement
__device__ float2 g_slots[EMAX];             // {w, bitcast(src)} per CSR slot
__device__ float  g_x[(size_t)NMAX * COUT];  // features @ Wlin + blin
__device__ float  g_colstats[2 * COUT];      // [0:128) sum, [128:256) sumsq
__device__ int    g_partials[128];           // scan block partials (<= 98 used)

// ---------------- zeroing (split per dependency chain) ----------------------
__global__ void zeroA_kernel(int N) {        // default stream: normals
    int i = blockIdx.x * blockDim.x + threadIdx.x;
    if (i < N * 3) g_normals[i] = 0.f;
}

__global__ void zeroB_kernel(int N) {        // side stream: counts + colstats
    int i = blockIdx.x * blockDim.x + threadIdx.x;
    if (i < N) g_counts[i] = 0;
    if (i < 2 * COUT) g_colstats[i] = 0.f;
}

// ---------------- face normals: scatter cross products ----------------------
__global__ void face_kernel(const float* __restrict__ vtx,
                            const int* __restrict__ faces, int F) {
    int f = blockIdx.x * blockDim.x + threadIdx.x;
    if (f >= F) return;
    int i0 = faces[f], i1 = faces[F + f], i2 = faces[2 * F + f];
    float v0x = vtx[3 * i0], v0y = vtx[3 * i0 + 1], v0z = vtx[3 * i0 + 2];
    float v1x = vtx[3 * i1], v1y = vtx[3 * i1 + 1], v1z = vtx[3 * i1 + 2];
    float v2x = vtx[3 * i2], v2y = vtx[3 * i2 + 1], v2z = vtx[3 * i2 + 2];
    float ax = v1x - v0x, ay = v1y - v0y, az = v1z - v0z;
    float bx = v2x - v0x, by = v2y - v0y, bz = v2z - v0z;
    float nx = ay * bz - az * by;
    float ny = az * bx - ax * bz;
    float nz = ax * by - ay * bx;
    atomicAdd(&g_normals[3 * i0 + 0], nx);
    atomicAdd(&g_normals[3 * i0 + 1], ny);
    atomicAdd(&g_normals[3 * i0 + 2], nz);
    atomicAdd(&g_normals[3 * i1 + 0], nx);
    atomicAdd(&g_normals[3 * i1 + 1], ny);
    atomicAdd(&g_normals[3 * i1 + 2], nz);
    atomicAdd(&g_normals[3 * i2 + 0], nx);
    atomicAdd(&g_normals[3 * i2 + 1], ny);
    atomicAdd(&g_normals[3 * i2 + 2], nz);
}

// ---------------- in-degree histogram (side stream; only needs edges) -------
__global__ void hist_kernel(const int* __restrict__ edges, int E) {
    int e = blockIdx.x * blockDim.x + threadIdx.x;
    if (e >= E) return;
    atomicAdd(&g_counts[edges[E + e]], 1);
}

// ---------------- scan over counts (2 kernels) -------------------------------
__device__ __forceinline__ int block_excl_scan(int v) {
    __shared__ int sm[32];
    int lane = threadIdx.x & 31, wid = threadIdx.x >> 5;
    int nw = blockDim.x >> 5;
    int incl = v;
#pragma unroll
    for (int o = 1; o < 32; o <<= 1) {
        int n = __shfl_up_sync(0xffffffffu, incl, o);
        if (lane >= o) incl += n;
    }
    if (lane == 31) sm[wid] = incl;
    __syncthreads();
    if (wid == 0) {
        int ws = (lane < nw) ? sm[lane] : 0;
#pragma unroll
        for (int o = 1; o < 32; o <<= 1) {
            int n = __shfl_up_sync(0xffffffffu, ws, o);
            if (lane >= o) ws += n;
        }
        if (lane < nw) sm[lane] = ws;
    }
    __syncthreads();
    int base = wid ? sm[wid - 1] : 0;
    return base + incl - v;
}

__global__ void scanA_kernel(int N) {  // per-block sums of counts
    __shared__ int sm[32];
    int i = blockIdx.x * 1024 + threadIdx.x;
    int v = (i < N) ? g_counts[i] : 0;
#pragma unroll
    for (int o = 16; o; o >>= 1) v += __shfl_down_sync(0xffffffffu, v, o);
    if ((threadIdx.x & 31) == 0) sm[threadIdx.x >> 5] = v;
    __syncthreads();
    if (threadIdx.x < 32) {
        int w = sm[threadIdx.x];
#pragma unroll
        for (int o = 16; o; o >>= 1) w += __shfl_down_sync(0xffffffffu, w, o);
        if (threadIdx.x == 0) g_partials[blockIdx.x] = w;
    }
}

// Fused scanB+scanC: every block redundantly prefix-sums the <=98 partials
// from smem (uniform, ~100 LDS), then block-scans its counts chunk.
__global__ void scanBC_kernel(int N, int NB) {
    __shared__ int spart[128];
    int t = threadIdx.x;
    if (t < 128) spart[t] = (t < NB) ? g_partials[t] : 0;
    __syncthreads();
    int base = 0;
    for (int j = 0; j < blockIdx.x; ++j) base += spart[j];
    int i = blockIdx.x * 1024 + t;
    int v = (i < N) ? g_counts[i] : 0;
    int ex = block_excl_scan(v);
    if (i < N) {
        int s = base + ex;
        g_start[i] = s;
        g_cursor[i] = s;
    }
}

// ---- per-edge: inline normal-normalize + metric MLP + direct CSR place -----
__global__ void edgeplace_kernel(const float* __restrict__ vtx,
                                 const int* __restrict__ edges,
                                 const float* __restrict__ W1,
                                 const float* __restrict__ b1,
                                 const float* __restrict__ W2,
                                 const float* __restrict__ b2, int E) {
    __shared__ float sW1[96], sb1[32], sW2[192], sb2[6];
    int tid = threadIdx.x;
    if (tid < 96) sW1[tid] = W1[tid];
    if (tid < 32) sb1[tid] = b1[tid];
    if (tid < 192) sW2[tid] = W2[tid];
    if (tid < 6) sb2[tid] = b2[tid];
    __syncthreads();

    int e = blockIdx.x * blockDim.x + tid;
    if (e >= E) return;
    int src = edges[e], dst = edges[E + e];

    float sx = vtx[3 * src], sy = vtx[3 * src + 1], sz = vtx[3 * src + 2];
    float dx = vtx[3 * dst] - sx;
    float dy = vtx[3 * dst + 1] - sy;
    float dz = vtx[3 * dst + 2] - sz;
    // normalize raw accumulated normal inline (same formula as reference)
    float nx = g_normals[3 * src], ny = g_normals[3 * src + 1], nz = g_normals[3 * src + 2];
    float nn = sqrtf(nx * nx + ny * ny + nz * nz);
    float ninv = 1.f / (nn + 1e-8f);
    nx *= ninv; ny *= ninv; nz *= ninv;

    float dn = dx * nx + dy * ny + dz * nz;
    float t0 = dx - dn * nx, t1 = dy - dn * ny, t2 = dz - dn * nz;

    float th0 = sb2[0], th1 = sb2[1], th2 = sb2[2], th3 = sb2[3], th4 = sb2[4], th5 = sb2[5];
#pragma unroll
    for (int j = 0; j < 32; ++j) {
        float hv = t0 * sW1[j] + t1 * sW1[32 + j] + t2 * sW1[64 + j] + sb1[j];
        hv = fmaxf(hv, 0.f);
        th0 += hv * sW2[j * 6 + 0];
        th1 += hv * sW2[j * 6 + 1];
        th2 += hv * sW2[j * 6 + 2];
        th3 += hv * sW2[j * 6 + 3];
        th4 += hv * sW2[j * 6 + 4];
        th5 += hv * sW2[j * 6 + 5];
    }
    // S sym => q = t' S S t = ||S t||^2
    float u0 = th0 * t0 + th1 * t1 + th2 * t2;
    float u1 = th1 * t0 + th3 * t1 + th4 * t2;
    float u2 = th2 * t0 + th4 * t1 + th5 * t2;
    float q = u0 * u0 + u1 * u1 + u2 * u2;
    float w = expf(-q);

    int slot = atomicAdd(&g_cursor[dst], 1);
    g_slots[slot] = make_float2(w, __int_as_float(src));
}

// ---------------- GEMM: x = features @ Wlin + blin  (fp32, packed f32x2) ----
__global__ void __launch_bounds__(256, 1)
gemm_kernel(const float* __restrict__ A, const float* __restrict__ W,
            const float* __restrict__ bias, int N) {
    __shared__ float Bs[64 * 128];  // 32 KB
    int tid = threadIdx.x;
    int tx = tid & 15, ty = tid >> 4;
    int row0 = blockIdx.x * 128 + ty * 8;

    unsigned long long acc[8][4];
#pragma unroll
    for (int i = 0; i < 8; ++i)
#pragma unroll
        for (int j = 0; j < 4; ++j) acc[i][j] = 0ull;

    const float4* A4 = (const float4*)A;
    const float4* W4 = (const float4*)W;
    float4* Bs4 = (float4*)Bs;

    for (int h = 0; h < 2; ++h) {
        __syncthreads();
#pragma unroll
        for (int i = 0; i < 8; ++i) Bs4[tid + i * 256] = W4[h * 2048 + tid + i * 256];
        __syncthreads();

        for (int k4 = 0; k4 < 16; ++k4) {
            int kk = h * 16 + k4;
            float4 av[8];
#pragma unroll
            for (int i = 0; i < 8; ++i) {
                int r = row0 + i;
                av[i] = (r < N) ? __ldg(&A4[(size_t)r * 32 + kk])
                                : make_float4(0.f, 0.f, 0.f, 0.f);
            }
#pragma unroll
            for (int s = 0; s < 4; ++s) {
                const unsigned long long* brow =
                    (const unsigned long long*)&Bs[(k4 * 4 + s) * 128];
                unsigned long long b0 = brow[tx];
                unsigned long long b1 = brow[16 + tx];
                unsigned long long b2 = brow[32 + tx];
                unsigned long long b3 = brow[48 + tx];
#pragma unroll
                for (int i = 0; i < 8; ++i) {
                    float a = (s == 0) ? av[i].x : (s == 1) ? av[i].y
                              : (s == 2) ? av[i].z : av[i].w;
                    unsigned int au = __float_as_uint(a);
                    unsigned long long pa;
                    asm("mov.b64 %0, {%1, %2};" : "=l"(pa) : "r"(au), "r"(au));
                    asm("fma.rn.f32x2 %0, %1, %2, %0;" : "+l"(acc[i][0]) : "l"(pa), "l"(b0));
                    asm("fma.rn.f32x2 %0, %1, %2, %0;" : "+l"(acc[i][1]) : "l"(pa), "l"(b1));
                    asm("fma.rn.f32x2 %0, %1, %2, %0;" : "+l"(acc[i][2]) : "l"(pa), "l"(b2));
                    asm("fma.rn.f32x2 %0, %1, %2, %0;" : "+l"(acc[i][3]) : "l"(pa), "l"(b3));
                }
            }
        }
    }

    const unsigned long long* bias2 = (const unsigned long long*)bias;
    unsigned long long bb[4];
#pragma unroll
    for (int j = 0; j < 4; ++j) bb[j] = bias2[j * 16 + tx];

#pragma unroll
    for (int i = 0; i < 8; ++i) {
        int r = row0 + i;
        if (r >= N) break;
        unsigned long long* orow = (unsigned long long*)&g_x[(size_t)r * 128];
#pragma unroll
        for (int j = 0; j < 4; ++j) {
            unsigned long long res;
            asm("add.rn.f32x2 %0, %1, %2;" : "=l"(res) : "l"(acc[i][j]), "l"(bb[j]));
            orow[j * 16 + tx] = res;
        }
    }
}

// ---- warp-per-vertex weighted-mean aggregation + fused column stats --------
__global__ void __launch_bounds__(256)
aggregate_kernel(float* __restrict__ out, int N) {
    __shared__ float sstat[256];
    int tid = threadIdx.x;
    sstat[tid] = 0.f;
    __syncthreads();

    int lane = tid & 31;
    int wwarp = tid >> 5;
    int vstart = blockIdx.x * 8 + wwarp;
    int vstride = gridDim.x * 8;

    const float4* X4 = (const float4*)g_x;
    float s0 = 0.f, s1 = 0.f, s2 = 0.f, s3 = 0.f;
    float q0 = 0.f, q1 = 0.f, q2 = 0.f, q3 = 0.f;

    for (int v = vstart; v < N; v += vstride) {
        int base = g_start[v];
        int deg = g_counts[v];
        float4 acc = make_float4(0.f, 0.f, 0.f, 0.f);
        float wsum = 0.f;
        int it = 0;
        for (; it + 1 < deg; it += 2) {
            float2 sa = g_slots[base + it];
            float2 sb = g_slots[base + it + 1];
            int srca = __float_as_int(sa.y);
            int srcb = __float_as_int(sb.y);
            float4 xa = X4[(size_t)srca * 32 + lane];
            float4 xb = X4[(size_t)srcb * 32 + lane];
            acc.x += sa.x * xa.x; acc.y += sa.x * xa.y;
            acc.z += sa.x * xa.z; acc.w += sa.x * xa.w;
            acc.x += sb.x * xb.x; acc.y += sb.x * xb.y;
            acc.z += sb.x * xb.z; acc.w += sb.x * xb.w;
            wsum += sa.x + sb.x;
        }
        if (it < deg) {
            float2 sl = g_slots[base + it];
            int src = __float_as_int(sl.y);
            float4 xv = X4[(size_t)src * 32 + lane];
            acc.x += sl.x * xv.x; acc.y += sl.x * xv.y;
            acc.z += sl.x * xv.z; acc.w += sl.x * xv.w;
            wsum += sl.x;
        }
        float inv = 1.f / (wsum + 1e-5f);
        float4 o = make_float4(acc.x * inv, acc.y * inv, acc.z * inv, acc.w * inv);
        ((float4*)out)[(size_t)v * 32 + lane] = o;
        s0 += o.x; s1 += o.y; s2 += o.z; s3 += o.w;
        q0 += o.x * o.x; q1 += o.y * o.y; q2 += o.z * o.z; q3 += o.w * o.w;
    }

    int c = lane * 4;
    atomicAdd(&sstat[c + 0], s0);
    atomicAdd(&sstat[c + 1], s1);
    atomicAdd(&sstat[c + 2], s2);
    atomicAdd(&sstat[c + 3], s3);
    atomicAdd(&sstat[128 + c + 0], q0);
    atomicAdd(&sstat[128 + c + 1], q1);
    atomicAdd(&sstat[128 + c + 2], q2);
    atomicAdd(&sstat[128 + c + 3], q3);
    __syncthreads();
    atomicAdd(&g_colstats[tid], sstat[tid]);
}

// ---------------- normalize + ELU (stats finalization folded in) ------------
__global__ void norm_elu_kernel(float* __restrict__ out, int N) {
    __shared__ float smu[128], sinv[128];
    int tid = threadIdx.x;
    if (tid < 128) {
        float s = g_colstats[tid], q = g_colstats[128 + tid];
        float mu = s / (float)N;
        float var = (q - (float)N * mu * mu) / (float)(N - 1);
        var = fmaxf(var, 0.f);
        smu[tid] = mu;
        sinv[tid] = 1.f / (sqrtf(var) + 1e-5f);
    }
    __syncthreads();

    int total = N * 32;  // float4 count
    for (int i = blockIdx.x * blockDim.x + tid; i < total;
         i += gridDim.x * blockDim.x) {
        float4 v = ((float4*)out)[i];
        int c = (i & 31) * 4;
        float z;
        z = (v.x - smu[c + 0]) * sinv[c + 0]; v.x = z > 0.f ? z : expm1f(z);
        z = (v.y - smu[c + 1]) * sinv[c + 1]; v.y = z > 0.f ? z : expm1f(z);
        z = (v.z - smu[c + 2]) * sinv[c + 2]; v.z = z > 0.f ? z : expm1f(z);
        z = (v.w - smu[c + 3]) * sinv[c + 3]; v.w = z > 0.f ? z : expm1f(z);
        ((float4*)out)[i] = v;
    }
}

// ---------------- launcher ---------------------------------------------------
extern "C" void kernel_launch(void* const* d_in, const int* in_sizes, int n_in,
                              void* d_out, int out_size) {
    const float* features = (const float*)d_in[0];
    const float* vertices = (const float*)d_in[1];
    const int*   edges    = (const int*)d_in[2];
    const int*   faces    = (const int*)d_in[3];
    const float* W1       = (const float*)d_in[4];
    const float* b1       = (const float*)d_in[5];
    const float* W2       = (const float*)d_in[6];
    const float* b2       = (const float*)d_in[7];
    const float* Wlin     = (const float*)d_in[8];
    const float* blin     = (const float*)d_in[9];
    float* out = (float*)d_out;

    int N = in_sizes[0] / CIN;
    int E = in_sizes[2] / 2;
    int F = in_sizes[3] / 3;
    if (N > NMAX) N = NMAX;
    if (E > EMAX) E = EMAX;

    // One-time host resources (created on the uncaptured correctness call).
    static cudaStream_t s2 = nullptr, s3 = nullptr;
    static cudaEvent_t evFork = nullptr, evJoin = nullptr, evScan = nullptr;
    if (s2 == nullptr) {
        cudaStreamCreateWithFlags(&s2, cudaStreamNonBlocking);
        cudaStreamCreateWithFlags(&s3, cudaStreamNonBlocking);
        cudaEventCreateWithFlags(&evFork, cudaEventDisableTiming);
        cudaEventCreateWithFlags(&evJoin, cudaEventDisableTiming);
        cudaEventCreateWithFlags(&evScan, cudaEventDisableTiming);
    }

    int NB = (N + 1023) / 1024;

    // Fork point.
    cudaEventRecord(evFork, 0);

    // Stream s2: GEMM (independent of everything else).
    cudaStreamWaitEvent(s2, evFork, 0);
    gemm_kernel<<<(N + 127) / 128, 256, 0, s2>>>(features, Wlin, blin, N);
    cudaEventRecord(evJoin, s2);

    // Stream s3: in-degree histogram + scan (needs only edges).
    cudaStreamWaitEvent(s3, evFork, 0);
    zeroB_kernel<<<(N + 255) / 256, 256, 0, s3>>>(N);
    hist_kernel<<<(E + 255) / 256, 256, 0, s3>>>(edges, E);
    scanA_kernel<<<NB, 1024, 0, s3>>>(N);
    scanBC_kernel<<<NB, 1024, 0, s3>>>(N, NB);
    cudaEventRecord(evScan, s3);

    // Default stream: geometry chain.
    zeroA_kernel<<<(N * 3 + 255) / 256, 256>>>(N);
    face_kernel<<<(F + 255) / 256, 256>>>(vertices, faces, F);

    // edgeplace needs face normals (this stream) + CSR cursors (s3).
    cudaStreamWaitEvent(0, evScan, 0);
    edgeplace_kernel<<<(E + 255) / 256, 256>>>(vertices, edges, W1, b1, W2, b2, E);

    // aggregation needs slots (this stream) + x (s2).
    cudaStreamWaitEvent(0, evJoin, 0);
    aggregate_kernel<<<1184, 256>>>(out, N);
    norm_elu_kernel<<<1184, 256>>>(out, N);
}